// round 16
// baseline (speedup 1.0000x reference)
#include <cuda_runtime.h>
#include <cuda_fp16.h>
#include <cstdint>

#define BB 128
#define SS 4096
#define CC 64
#define TILE 128
#define NW 8
#define THREADS (NW * 32)
#define TILES_PER_B (SS / TILE)          // 32
#define TT (BB * TILES_PER_B)            // 4096 tiles total

#define SA 72
#define SB 72
#define OFF_X0 0                  // [129][64] f32 logits buf 0 = 33024
#define OFF_X1 33024              // buf 1
#define OFF_A  66048              // [129][72] f16            = 18576
#define OFF_B  84624              // [72][72]  f16 M^T,u,w,0  = 10368
#define OFF_U  94992
#define OFF_W  95248
#define OFF_T  95504              // f32[132] lse
#define OFF_T2 96032              // f32x2[130] (du, dw)
#define OFF_MS 97072
#define SMEM_TOTAL 97080

#define MMA16816(d,a,b0,b1)                                                   \
    asm volatile("mma.sync.aligned.m16n8k16.row.col.f32.f16.f16.f32 "         \
        "{%0,%1,%2,%3}, {%4,%5,%6,%7}, {%8,%9}, {%0,%1,%2,%3};"               \
        : "+f"((d)[0]), "+f"((d)[1]), "+f"((d)[2]), "+f"((d)[3])              \
        : "r"((a)[0]), "r"((a)[1]), "r"((a)[2]), "r"((a)[3]), "r"(b0), "r"(b1))

#define LDSM4(r0,r1,r2,r3,addr)                                               \
    asm volatile("ldmatrix.sync.aligned.m8n8.x4.shared.b16 {%0,%1,%2,%3}, [%4];" \
        : "=r"(r0), "=r"(r1), "=r"(r2), "=r"(r3) : "r"(addr))

#define LDSM2(r0,r1,addr)                                                     \
    asm volatile("ldmatrix.sync.aligned.m8n8.x2.shared.b16 {%0,%1}, [%2];"    \
        : "=r"(r0), "=r"(r1) : "r"(addr))

static __device__ __forceinline__ uint32_t smem_u32(const void* p) {
    uint32_t a;
    asm("{ .reg .u64 t; cvta.to.shared.u64 t, %1; cvt.u32.u64 %0, t; }" : "=r"(a) : "l"(p));
    return a;
}

__device__ __forceinline__ float2 ffma2(float2 a, float2 b, float2 c) {
    float2 d;
    asm("{ .reg .b64 ra, rb, rc, rd;\n\t"
        "mov.b64 ra, {%2, %3}; mov.b64 rb, {%4, %5}; mov.b64 rc, {%6, %7};\n\t"
        "fma.rn.f32x2 rd, ra, rb, rc;\n\t"
        "mov.b64 {%0, %1}, rd; }"
        : "=f"(d.x), "=f"(d.y)
        : "f"(a.x), "f"(a.y), "f"(b.x), "f"(b.y), "f"(c.x), "f"(c.y));
    return d;
}
__device__ __forceinline__ float2 fmul2(float2 a, float2 b) {
    float2 d;
    asm("{ .reg .b64 ra, rb, rd;\n\t"
        "mov.b64 ra, {%2, %3}; mov.b64 rb, {%4, %5};\n\t"
        "mul.rn.f32x2 rd, ra, rb;\n\t"
        "mov.b64 {%0, %1}, rd; }"
        : "=f"(d.x), "=f"(d.y)
        : "f"(a.x), "f"(a.y), "f"(b.x), "f"(b.y));
    return d;
}

// paired exp(x) on FMA/ALU pipes (no MUFU)
__device__ __forceinline__ float2 fast_exp2x(float2 x) {
    const float L2E   = 1.4426950408889634f;
    const float MAGIC = 12582912.0f;
    float2 y = fmul2(x, make_float2(L2E, L2E));
    float2 t = ffma2(y, make_float2(1.f, 1.f), make_float2(MAGIC, MAGIC));
    float2 n = ffma2(t, make_float2(1.f, 1.f), make_float2(-MAGIC, -MAGIC));
    float2 f = ffma2(n, make_float2(-1.f, -1.f), y);
    float2 p = make_float2(1.3333558146428443e-3f, 1.3333558146428443e-3f);
    p = ffma2(p, f, make_float2(9.6181291076284772e-3f, 9.6181291076284772e-3f));
    p = ffma2(p, f, make_float2(5.5504108664798463e-2f, 5.5504108664798463e-2f));
    p = ffma2(p, f, make_float2(2.4022650695910072e-1f, 2.4022650695910072e-1f));
    p = ffma2(p, f, make_float2(6.9314718055994531e-1f, 6.9314718055994531e-1f));
    p = ffma2(p, f, make_float2(1.0f, 1.0f));
    float2 sc;
    sc.x = __int_as_float((__float_as_int(t.x) - 0x4B400000 + 127) << 23);
    sc.y = __int_as_float((__float_as_int(t.y) - 0x4B400000 + 127) << 23);
    return fmul2(p, sc);
}

// softmax-sum + store for 4 token rows (2 tokens per warp half)
__device__ __forceinline__ void proc_tokens(
    const float4* xv, int tbase, int half, int qi,
    __half* A, float* tbl)
{
    float s[4];
    #pragma unroll
    for (int j = 0; j < 4; j++) {
        float2 e0 = fast_exp2x(make_float2(xv[j].x, xv[j].y));
        float2 e1 = fast_exp2x(make_float2(xv[j].z, xv[j].w));
        s[j] = (e0.x + e0.y) + (e1.x + e1.y);
    }
    #pragma unroll
    for (int o = 8; o; o >>= 1) {
        #pragma unroll
        for (int j = 0; j < 4; j++)
            s[j] += __shfl_xor_sync(0xffffffffu, s[j], o);
    }
    #pragma unroll
    for (int j = 0; j < 4; j++) {
        int t = tbase + 2 * j + half;
        if (qi == 0) tbl[t] = __logf(s[j]);
        __half2 h01 = __floats2half2_rn(xv[j].x, xv[j].y);
        __half2 h23 = __floats2half2_rn(xv[j].z, xv[j].w);
        *(uint2*)&A[t * SA + 4 * qi] = make_uint2(*(uint32_t*)&h01, *(uint32_t*)&h23);
    }
}

// issue cp.async for one tile's logits into X buffer
__device__ __forceinline__ void prefetch_tile(
    const float* logits, int tile, uint32_t dst, int tid)
{
    int b  = tile >> 5;                       // / TILES_PER_B
    int t0 = (tile & 31) * TILE;
    int n4 = min(TILE + 1, SS - t0) * 16;
    const float4* src = (const float4*)(logits + ((size_t)b * SS + t0) * CC);
    #pragma unroll 4
    for (int i = tid; i < n4; i += THREADS)
        asm volatile("cp.async.cg.shared.global [%0], [%1], 16;"
                     :: "r"(dst + i * 16), "l"(src + i) : "memory");
    asm volatile("cp.async.commit_group;" ::: "memory");
}

__global__ __launch_bounds__(THREADS, 2) void pk_kernel(
    const float* __restrict__ logits,
    const float* __restrict__ M,
    float* __restrict__ out)
{
    extern __shared__ char dsm[];
    __half*  A    = (__half*)(dsm + OFF_A);
    __half*  Bm   = (__half*)(dsm + OFF_B);
    float*   su   = (float*)(dsm + OFF_U);
    float*   sw   = (float*)(dsm + OFF_W);
    float*   tbl  = (float*)(dsm + OFF_T);
    float2*  tbl2 = (float2*)(dsm + OFF_T2);
    const uint32_t sb = smem_u32(dsm);

    const int tid  = threadIdx.x;
    const int w    = tid >> 5;
    const int lane = tid & 31;
    const int G    = gridDim.x;

    int tile = blockIdx.x;
    if (tile < TT) prefetch_tile(logits, tile, sb + OFF_X0, tid);

    // ---- stage B rows 0..63 = M^T (f16); zero rows 66..71; u, w ----
    for (int idx = tid; idx < CC * CC; idx += THREADS) {
        int k = idx >> 6, n = idx & 63;
        Bm[n * SB + k] = __float2half(M[idx]);
    }
    for (int idx = tid; idx < 6 * 64; idx += THREADS) {
        int rr = 66 + (idx >> 6), k = idx & 63;
        Bm[rr * SB + k] = __float2half(0.f);
    }
    if (tid < 64) {
        const float4* rr = (const float4*)(M + tid * CC);
        float s = 0.f;
        #pragma unroll
        for (int i = 0; i < 16; i++) { float4 v = rr[i]; s += (v.x + v.y) + (v.z + v.w); }
        su[tid] = s;
    } else if (tid < 128) {
        int c = tid - 64;
        float s = 0.f;
        #pragma unroll 8
        for (int d = 0; d < 64; d++) s += M[d * CC + c];
        sw[c] = s;
    }
    __syncthreads();
    if (tid < 64) {
        Bm[64 * SB + tid] = __float2half(su[tid]);
        Bm[65 * SB + tid] = __float2half(sw[tid]);
    }
    if (tid == 0) {
        float s = 0.f;
        #pragma unroll
        for (int i = 0; i < 64; i++) s += su[i];
        *(float*)(dsm + OFF_MS) = s;
    }

    // lane-invariant addresses
    const int half = lane >> 4;
    const int qi   = lane & 15;
    const int g    = lane >> 2;
    const int t4   = lane & 3;
    const int rb   = w * 16;
    const int q    = lane >> 3;
    const int r    = lane & 7;
    const uint32_t aAddr = sb + OFF_A + (uint32_t)(((rb + r + (q & 1) * 8) * SA + (q >> 1) * 8) * 2);
    const uint32_t bAddr = sb + OFF_B + (uint32_t)(((r + (q >> 1) * 8) * SB + (q & 1) * 8) * 2);
    const uint32_t eAddr = sb + OFF_A + (uint32_t)(((rb + 1 + r + (q & 1) * 8) * SA + (q >> 1) * 8) * 2);
    const uint32_t b2Addr = sb + OFF_B +
        (uint32_t)(((64 + (lane & 7)) * SB + ((lane >> 3) & 1) * 8) * 2);

    int buf = 0;
    for (; tile < TT; tile += G, buf ^= 1) {
        const int b  = tile >> 5;
        const int t0 = (tile & 31) * TILE;
        const int ntok = min(TILE + 1, SS - t0);
        const int nout = min(TILE, SS - 1 - t0);

        // prefetch this CTA's next tile into the other buffer, wait for current
        const int nxt = tile + G;
        if (nxt < TT) {
            prefetch_tile(logits, nxt, sb + (buf ? OFF_X0 : OFF_X1), tid);
            asm volatile("cp.async.wait_group 1;" ::: "memory");
        } else {
            asm volatile("cp.async.wait_group 0;" ::: "memory");
        }
        __syncthreads();   // x ready; previous iteration's A reads done

        const float4* xs = (const float4*)(dsm + (buf ? OFF_X1 : OFF_X0));

        // ---- phase 1 ----
        float4 xA[4], xB[4];
        #pragma unroll
        for (int j = 0; j < 4; j++) xA[j] = xs[(w * 8 + 2 * j + half) * 16 + qi];
        #pragma unroll
        for (int j = 0; j < 4; j++) xB[j] = xs[(64 + w * 8 + 2 * j + half) * 16 + qi];
        const bool has_tail = (w == 0) && (ntok > TILE);
        float4 xC = make_float4(0.f, 0.f, 0.f, 0.f);
        if (has_tail) xC = xs[TILE * 16 + qi];

        proc_tokens(xA, w * 8, half, qi, A, tbl);
        proc_tokens(xB, 64 + w * 8, half, qi, A, tbl);

        if (has_tail) {
            float2 e0 = fast_exp2x(make_float2(xC.x, xC.y));
            float2 e1 = fast_exp2x(make_float2(xC.z, xC.w));
            float sC = (e0.x + e0.y) + (e1.x + e1.y);
            const float4 wv = ((const float4*)sw)[qi];
            float dwC = fmaf(xC.x, wv.x, fmaf(xC.y, wv.y, fmaf(xC.z, wv.z, xC.w * wv.w)));
            #pragma unroll
            for (int o = 8; o; o >>= 1) {
                sC  += __shfl_xor_sync(0xffffffffu, sC, o);
                dwC += __shfl_xor_sync(0xffffffffu, dwC, o);
            }
            if (half == 0) {
                if (qi == 0) {
                    tbl[TILE]  = __logf(sC);
                    tbl2[TILE] = make_float2(0.f, dwC);
                }
                __half2 h01 = __floats2half2_rn(xC.x, xC.y);
                __half2 h23 = __floats2half2_rn(xC.z, xC.w);
                *(uint2*)&A[TILE * SA + 4 * qi] =
                    make_uint2(*(uint32_t*)&h01, *(uint32_t*)&h23);
            }
        }
        __syncthreads();

        // ---- phase 2 ----
        uint32_t af[4][4];
        #pragma unroll
        for (int kc = 0; kc < 4; kc++)
            LDSM4(af[kc][0], af[kc][1], af[kc][2], af[kc][3], aAddr + kc * 32);

        float v0 = 0.f, v1 = 0.f;

        #pragma unroll
        for (int ncp = 0; ncp < 4; ncp++) {
            float d0[4] = {0.f, 0.f, 0.f, 0.f};
            float d1[4] = {0.f, 0.f, 0.f, 0.f};
            const uint32_t bOff = bAddr + (uint32_t)(ncp * 16 * SB * 2);

            #pragma unroll
            for (int kc = 0; kc < 4; kc++) {
                uint32_t b0, b1, b2, b3;
                LDSM4(b0, b1, b2, b3, bOff + kc * 32);
                MMA16816(d0, af[kc], b0, b1);
                MMA16816(d1, af[kc], b2, b3);
            }

            uint32_t ph[4];
            LDSM4(ph[0], ph[1], ph[2], ph[3], eAddr + ncp * 32);

            #pragma unroll
            for (int m = 0; m < 4; m++) {
                __half2 h = *(__half2*)&ph[m];
                float px = __low2float(h);
                float py = __high2float(h);
                const float* dd = (m & 2) ? d1 : d0;
                if (m & 1) {
                    v1 = fmaf(dd[2], px, v1);
                    v1 = fmaf(dd[3], py, v1);
                } else {
                    v0 = fmaf(dd[0], px, v0);
                    v0 = fmaf(dd[1], py, v0);
                }
            }
        }

        {   // extra n-chunk: cols 64 (u), 65 (w)
            float d64[4] = {0.f, 0.f, 0.f, 0.f};
            #pragma unroll
            for (int kc = 0; kc < 4; kc++) {
                uint32_t bb0, bb1;
                LDSM2(bb0, bb1, b2Addr + kc * 32);
                MMA16816(d64, af[kc], bb0, bb1);
            }
            if (t4 == 0) {
                tbl2[rb + g]     = make_float2(d64[0], d64[1]);
                tbl2[rb + g + 8] = make_float2(d64[2], d64[3]);
            }
        }

        v0 += __shfl_xor_sync(0xffffffffu, v0, 1);
        v0 += __shfl_xor_sync(0xffffffffu, v0, 2);
        v1 += __shfl_xor_sync(0xffffffffu, v1, 1);
        v1 += __shfl_xor_sync(0xffffffffu, v1, 2);

        __syncthreads();

        if (t4 == 0) {
            const float ms = *(const float*)(dsm + OFF_MS);
            float* outp = out + (size_t)b * (SS - 1) + t0;
            int i0 = rb + g, i1 = rb + g + 8;
            if (i0 < nout) {
                float l0 = tbl[i0], l1 = tbl[i0 + 1];
                outp[i0] = v0 - l1 * tbl2[i0].x - l0 * tbl2[i0 + 1].y + l0 * l1 * ms;
            }
            if (i1 < nout) {
                float l0 = tbl[i1], l1 = tbl[i1 + 1];
                outp[i1] = v1 - l1 * tbl2[i1].x - l0 * tbl2[i1 + 1].y + l0 * l1 * ms;
            }
        }
    }
}

extern "C" void kernel_launch(void* const* d_in, const int* in_sizes, int n_in,
                              void* d_out, int out_size)
{
    const float* logits = (const float*)d_in[0];
    const float* M      = (const float*)d_in[1];
    float* out          = (float*)d_out;

    int sms = 148;
    cudaDeviceGetAttribute(&sms, cudaDevAttrMultiProcessorCount, 0);
    int grid = 2 * sms;
    if (grid > TT) grid = TT;

    cudaFuncSetAttribute(pk_kernel, cudaFuncAttributeMaxDynamicSharedMemorySize, SMEM_TOTAL);
    pk_kernel<<<grid, THREADS, SMEM_TOTAL>>>(logits, M, out);
}

// round 17
// speedup vs baseline: 1.0115x; 1.0115x over previous
#include <cuda_runtime.h>
#include <cuda_fp16.h>
#include <cstdint>

#define BB 128
#define SS 4096
#define CC 64
#define TILE 128
#define NW 8
#define THREADS (NW * 32)
#define TILES_PER_B (SS / TILE)          // 32
#define TT (BB * TILES_PER_B)            // 4096 tiles total

#define SA 72
#define SB 72
#define OFF_X0 0                  // [129][64] f32 logits buf 0 = 33024
#define OFF_X1 33024              // buf 1
#define OFF_A  66048              // [129][72] f16            = 18576
#define OFF_B  84624              // [72][72]  f16 M^T,u,w,0  = 10368
#define OFF_U  94992
#define OFF_W  95248
#define OFF_T  95504              // f32[132] lse
#define OFF_T2 96032              // f32x2[130] (du, dw)
#define OFF_MS 97072
#define SMEM_TOTAL 97080

#define MMA16816(d,a,b0,b1)                                                   \
    asm volatile("mma.sync.aligned.m16n8k16.row.col.f32.f16.f16.f32 "         \
        "{%0,%1,%2,%3}, {%4,%5,%6,%7}, {%8,%9}, {%0,%1,%2,%3};"               \
        : "+f"((d)[0]), "+f"((d)[1]), "+f"((d)[2]), "+f"((d)[3])              \
        : "r"((a)[0]), "r"((a)[1]), "r"((a)[2]), "r"((a)[3]), "r"(b0), "r"(b1))

#define LDSM4(r0,r1,r2,r3,addr)                                               \
    asm volatile("ldmatrix.sync.aligned.m8n8.x4.shared.b16 {%0,%1,%2,%3}, [%4];" \
        : "=r"(r0), "=r"(r1), "=r"(r2), "=r"(r3) : "r"(addr))

#define LDSM2(r0,r1,addr)                                                     \
    asm volatile("ldmatrix.sync.aligned.m8n8.x2.shared.b16 {%0,%1}, [%2];"    \
        : "=r"(r0), "=r"(r1) : "r"(addr))

static __device__ __forceinline__ uint32_t smem_u32(const void* p) {
    uint32_t a;
    asm("{ .reg .u64 t; cvta.to.shared.u64 t, %1; cvt.u32.u64 %0, t; }" : "=r"(a) : "l"(p));
    return a;
}

__device__ __forceinline__ float2 ffma2(float2 a, float2 b, float2 c) {
    float2 d;
    asm("{ .reg .b64 ra, rb, rc, rd;\n\t"
        "mov.b64 ra, {%2, %3}; mov.b64 rb, {%4, %5}; mov.b64 rc, {%6, %7};\n\t"
        "fma.rn.f32x2 rd, ra, rb, rc;\n\t"
        "mov.b64 {%0, %1}, rd; }"
        : "=f"(d.x), "=f"(d.y)
        : "f"(a.x), "f"(a.y), "f"(b.x), "f"(b.y), "f"(c.x), "f"(c.y));
    return d;
}
__device__ __forceinline__ float2 fmul2(float2 a, float2 b) {
    float2 d;
    asm("{ .reg .b64 ra, rb, rd;\n\t"
        "mov.b64 ra, {%2, %3}; mov.b64 rb, {%4, %5};\n\t"
        "mul.rn.f32x2 rd, ra, rb;\n\t"
        "mov.b64 {%0, %1}, rd; }"
        : "=f"(d.x), "=f"(d.y)
        : "f"(a.x), "f"(a.y), "f"(b.x), "f"(b.y));
    return d;
}

// paired exp(x) on FMA/ALU pipes (no MUFU)
__device__ __forceinline__ float2 fast_exp2x(float2 x) {
    const float L2E   = 1.4426950408889634f;
    const float MAGIC = 12582912.0f;
    float2 y = fmul2(x, make_float2(L2E, L2E));
    float2 t = ffma2(y, make_float2(1.f, 1.f), make_float2(MAGIC, MAGIC));
    float2 n = ffma2(t, make_float2(1.f, 1.f), make_float2(-MAGIC, -MAGIC));
    float2 f = ffma2(n, make_float2(-1.f, -1.f), y);
    float2 p = make_float2(1.3333558146428443e-3f, 1.3333558146428443e-3f);
    p = ffma2(p, f, make_float2(9.6181291076284772e-3f, 9.6181291076284772e-3f));
    p = ffma2(p, f, make_float2(5.5504108664798463e-2f, 5.5504108664798463e-2f));
    p = ffma2(p, f, make_float2(2.4022650695910072e-1f, 2.4022650695910072e-1f));
    p = ffma2(p, f, make_float2(6.9314718055994531e-1f, 6.9314718055994531e-1f));
    p = ffma2(p, f, make_float2(1.0f, 1.0f));
    float2 sc;
    sc.x = __int_as_float((__float_as_int(t.x) - 0x4B400000 + 127) << 23);
    sc.y = __int_as_float((__float_as_int(t.y) - 0x4B400000 + 127) << 23);
    return fmul2(p, sc);
}

// softmax-sum + store for 4 token rows (2 tokens per warp half)
__device__ __forceinline__ void proc_tokens(
    const float4* xv, int tbase, int half, int qi,
    __half* A, float* tbl)
{
    float s[4];
    #pragma unroll
    for (int j = 0; j < 4; j++) {
        float2 e0 = fast_exp2x(make_float2(xv[j].x, xv[j].y));
        float2 e1 = fast_exp2x(make_float2(xv[j].z, xv[j].w));
        s[j] = (e0.x + e0.y) + (e1.x + e1.y);
    }
    #pragma unroll
    for (int o = 8; o; o >>= 1) {
        #pragma unroll
        for (int j = 0; j < 4; j++)
            s[j] += __shfl_xor_sync(0xffffffffu, s[j], o);
    }
    #pragma unroll
    for (int j = 0; j < 4; j++) {
        int t = tbase + 2 * j + half;
        if (qi == 0) tbl[t] = __logf(s[j]);
        __half2 h01 = __floats2half2_rn(xv[j].x, xv[j].y);
        __half2 h23 = __floats2half2_rn(xv[j].z, xv[j].w);
        *(uint2*)&A[t * SA + 4 * qi] = make_uint2(*(uint32_t*)&h01, *(uint32_t*)&h23);
    }
}

// issue cp.async for one tile's logits into X buffer
__device__ __forceinline__ void prefetch_tile(
    const float* logits, int tile, uint32_t dst, int tid)
{
    int b  = tile >> 5;                       // / TILES_PER_B
    int t0 = (tile & 31) * TILE;
    int n4 = min(TILE + 1, SS - t0) * 16;
    const float4* src = (const float4*)(logits + ((size_t)b * SS + t0) * CC);
    #pragma unroll 4
    for (int i = tid; i < n4; i += THREADS)
        asm volatile("cp.async.cg.shared.global [%0], [%1], 16;"
                     :: "r"(dst + i * 16), "l"(src + i) : "memory");
    asm volatile("cp.async.commit_group;" ::: "memory");
}

__global__ __launch_bounds__(THREADS, 2) void pk_kernel(
    const float* __restrict__ logits,
    const float* __restrict__ M,
    float* __restrict__ out)
{
    extern __shared__ char dsm[];
    __half*  A    = (__half*)(dsm + OFF_A);
    __half*  Bm   = (__half*)(dsm + OFF_B);
    float*   su   = (float*)(dsm + OFF_U);
    float*   sw   = (float*)(dsm + OFF_W);
    float*   tbl  = (float*)(dsm + OFF_T);
    float2*  tbl2 = (float2*)(dsm + OFF_T2);
    const uint32_t sb = smem_u32(dsm);

    const int tid  = threadIdx.x;
    const int w    = tid >> 5;
    const int lane = tid & 31;
    const int G    = gridDim.x;

    int tile = blockIdx.x;
    if (tile < TT) prefetch_tile(logits, tile, sb + OFF_X0, tid);

    // ---- stage B rows 0..63 = M^T (f16); zero rows 66..71; u, w ----
    for (int idx = tid; idx < CC * CC; idx += THREADS) {
        int k = idx >> 6, n = idx & 63;
        Bm[n * SB + k] = __float2half(M[idx]);
    }
    for (int idx = tid; idx < 6 * 64; idx += THREADS) {
        int rr = 66 + (idx >> 6), k = idx & 63;
        Bm[rr * SB + k] = __float2half(0.f);
    }
    if (tid < 64) {
        const float4* rr = (const float4*)(M + tid * CC);
        float s = 0.f;
        #pragma unroll
        for (int i = 0; i < 16; i++) { float4 v = rr[i]; s += (v.x + v.y) + (v.z + v.w); }
        su[tid] = s;
    } else if (tid < 128) {
        int c = tid - 64;
        float s = 0.f;
        #pragma unroll 8
        for (int d = 0; d < 64; d++) s += M[d * CC + c];
        sw[c] = s;
    }
    __syncthreads();
    if (tid < 64) {
        Bm[64 * SB + tid] = __float2half(su[tid]);
        Bm[65 * SB + tid] = __float2half(sw[tid]);
    }
    if (tid == 0) {
        float s = 0.f;
        #pragma unroll
        for (int i = 0; i < 64; i++) s += su[i];
        *(float*)(dsm + OFF_MS) = s;
    }

    // lane-invariant addresses
    const int half = lane >> 4;
    const int qi   = lane & 15;
    const int g    = lane >> 2;
    const int t4   = lane & 3;
    const int rb   = w * 16;
    const int q    = lane >> 3;
    const int r    = lane & 7;
    const uint32_t aAddr = sb + OFF_A + (uint32_t)(((rb + r + (q & 1) * 8) * SA + (q >> 1) * 8) * 2);
    const uint32_t bAddr = sb + OFF_B + (uint32_t)(((r + (q >> 1) * 8) * SB + (q & 1) * 8) * 2);
    const uint32_t eAddr = sb + OFF_A + (uint32_t)(((rb + 1 + r + (q & 1) * 8) * SA + (q >> 1) * 8) * 2);
    const uint32_t b2Addr = sb + OFF_B +
        (uint32_t)(((64 + (lane & 7)) * SB + ((lane >> 3) & 1) * 8) * 2);

    int buf = 0;
    for (; tile < TT; tile += G, buf ^= 1) {
        const int b  = tile >> 5;
        const int t0 = (tile & 31) * TILE;
        const int ntok = min(TILE + 1, SS - t0);
        const int nout = min(TILE, SS - 1 - t0);

        // prefetch this CTA's next tile into the other buffer, wait for current
        const int nxt = tile + G;
        if (nxt < TT) {
            prefetch_tile(logits, nxt, sb + (buf ? OFF_X0 : OFF_X1), tid);
            asm volatile("cp.async.wait_group 1;" ::: "memory");
        } else {
            asm volatile("cp.async.wait_group 0;" ::: "memory");
        }
        __syncthreads();   // x ready; previous iteration's A reads done

        const float4* xs = (const float4*)(dsm + (buf ? OFF_X1 : OFF_X0));

        // ---- phase 1 ----
        float4 xA[4], xB[4];
        #pragma unroll
        for (int j = 0; j < 4; j++) xA[j] = xs[(w * 8 + 2 * j + half) * 16 + qi];
        #pragma unroll
        for (int j = 0; j < 4; j++) xB[j] = xs[(64 + w * 8 + 2 * j + half) * 16 + qi];
        const bool has_tail = (w == 0) && (ntok > TILE);
        float4 xC = make_float4(0.f, 0.f, 0.f, 0.f);
        if (has_tail) xC = xs[TILE * 16 + qi];

        proc_tokens(xA, w * 8, half, qi, A, tbl);
        proc_tokens(xB, 64 + w * 8, half, qi, A, tbl);

        if (has_tail) {
            float2 e0 = fast_exp2x(make_float2(xC.x, xC.y));
            float2 e1 = fast_exp2x(make_float2(xC.z, xC.w));
            float sC = (e0.x + e0.y) + (e1.x + e1.y);
            const float4 wv = ((const float4*)sw)[qi];
            float dwC = fmaf(xC.x, wv.x, fmaf(xC.y, wv.y, fmaf(xC.z, wv.z, xC.w * wv.w)));
            #pragma unroll
            for (int o = 8; o; o >>= 1) {
                sC  += __shfl_xor_sync(0xffffffffu, sC, o);
                dwC += __shfl_xor_sync(0xffffffffu, dwC, o);
            }
            if (half == 0) {
                if (qi == 0) {
                    tbl[TILE]  = __logf(sC);
                    tbl2[TILE] = make_float2(0.f, dwC);
                }
                __half2 h01 = __floats2half2_rn(xC.x, xC.y);
                __half2 h23 = __floats2half2_rn(xC.z, xC.w);
                *(uint2*)&A[TILE * SA + 4 * qi] =
                    make_uint2(*(uint32_t*)&h01, *(uint32_t*)&h23);
            }
        }
        __syncthreads();

        // ---- phase 2 ----
        uint32_t af[4][4];
        #pragma unroll
        for (int kc = 0; kc < 4; kc++)
            LDSM4(af[kc][0], af[kc][1], af[kc][2], af[kc][3], aAddr + kc * 32);

        float v0 = 0.f, v1 = 0.f;

        #pragma unroll
        for (int ncp = 0; ncp < 4; ncp++) {
            float d0[4] = {0.f, 0.f, 0.f, 0.f};
            float d1[4] = {0.f, 0.f, 0.f, 0.f};
            const uint32_t bOff = bAddr + (uint32_t)(ncp * 16 * SB * 2);

            #pragma unroll
            for (int kc = 0; kc < 4; kc++) {
                uint32_t b0, b1, b2, b3;
                LDSM4(b0, b1, b2, b3, bOff + kc * 32);
                MMA16816(d0, af[kc], b0, b1);
                MMA16816(d1, af[kc], b2, b3);
            }

            uint32_t ph[4];
            LDSM4(ph[0], ph[1], ph[2], ph[3], eAddr + ncp * 32);

            #pragma unroll
            for (int m = 0; m < 4; m++) {
                __half2 h = *(__half2*)&ph[m];
                float px = __low2float(h);
                float py = __high2float(h);
                const float* dd = (m & 2) ? d1 : d0;
                if (m & 1) {
                    v1 = fmaf(dd[2], px, v1);
                    v1 = fmaf(dd[3], py, v1);
                } else {
                    v0 = fmaf(dd[0], px, v0);
                    v0 = fmaf(dd[1], py, v0);
                }
            }
        }

        {   // extra n-chunk: cols 64 (u), 65 (w)
            float d64[4] = {0.f, 0.f, 0.f, 0.f};
            #pragma unroll
            for (int kc = 0; kc < 4; kc++) {
                uint32_t bb0, bb1;
                LDSM2(bb0, bb1, b2Addr + kc * 32);
                MMA16816(d64, af[kc], bb0, bb1);
            }
            if (t4 == 0) {
                tbl2[rb + g]     = make_float2(d64[0], d64[1]);
                tbl2[rb + g + 8] = make_float2(d64[2], d64[3]);
            }
        }

        v0 += __shfl_xor_sync(0xffffffffu, v0, 1);
        v0 += __shfl_xor_sync(0xffffffffu, v0, 2);
        v1 += __shfl_xor_sync(0xffffffffu, v1, 1);
        v1 += __shfl_xor_sync(0xffffffffu, v1, 2);

        __syncthreads();

        if (t4 == 0) {
            const float ms = *(const float*)(dsm + OFF_MS);
            float* outp = out + (size_t)b * (SS - 1) + t0;
            int i0 = rb + g, i1 = rb + g + 8;
            if (i0 < nout) {
                float l0 = tbl[i0], l1 = tbl[i0 + 1];
                outp[i0] = v0 - l1 * tbl2[i0].x - l0 * tbl2[i0 + 1].y + l0 * l1 * ms;
            }
            if (i1 < nout) {
                float l0 = tbl[i1], l1 = tbl[i1 + 1];
                outp[i1] = v1 - l1 * tbl2[i1].x - l0 * tbl2[i1 + 1].y + l0 * l1 * ms;
            }
        }
    }
}

extern "C" void kernel_launch(void* const* d_in, const int* in_sizes, int n_in,
                              void* d_out, int out_size)
{
    const float* logits = (const float*)d_in[0];
    const float* M      = (const float*)d_in[1];
    float* out          = (float*)d_out;

    int sms = 148;
    cudaDeviceGetAttribute(&sms, cudaDevAttrMultiProcessorCount, 0);
    int grid = 2 * sms;
    if (grid > TT) grid = TT;

    cudaFuncSetAttribute(pk_kernel, cudaFuncAttributeMaxDynamicSharedMemorySize, SMEM_TOTAL);
    pk_kernel<<<grid, THREADS, SMEM_TOTAL>>>(logits, M, out);
}